// round 7
// baseline (speedup 1.0000x reference)
#include <cuda_runtime.h>
#include <cuda_fp16.h>
#include <cstdint>

// Problem constants
#define B_   1024
#define P_   24
#define H_   2048
#define K1_  4096   // H*R
#define N1_  2048   // H
#define K2_  2048
#define N2_  1024   // H/2
#define OUTP 4

// Scratch (allocation-free rule: __device__ globals)
__device__ __half g_xh [(size_t)B_ * P_ * H_];    // x   -> fp16
__device__ __half g_w1h[(size_t)P_ * K1_ * N1_];  // W1  -> fp16
__device__ __half g_w2h[(size_t)P_ * K2_ * N2_];  // W2  -> fp16
__device__ __half g_h1h[(size_t)P_ * B_ * N1_];   // layer1 out fp16
__device__ float  g_h2 [(size_t)P_ * B_ * N2_];   // layer2 out fp32

// ---------------------------------------------------------------------------
// helpers
// ---------------------------------------------------------------------------
__device__ __forceinline__ void mma_f16_f32(float* c, const uint32_t* a, const uint32_t* b) {
    asm volatile(
        "mma.sync.aligned.m16n8k16.row.col.f32.f16.f16.f32 "
        "{%0,%1,%2,%3}, {%4,%5,%6,%7}, {%8,%9}, {%0,%1,%2,%3};"
        : "+f"(c[0]), "+f"(c[1]), "+f"(c[2]), "+f"(c[3])
        : "r"(a[0]), "r"(a[1]), "r"(a[2]), "r"(a[3]), "r"(b[0]), "r"(b[1]));
}
__device__ __forceinline__ void mma_f16_f16(uint32_t* c, const uint32_t* a, const uint32_t* b) {
    asm volatile(
        "mma.sync.aligned.m16n8k16.row.col.f16.f16.f16.f16 "
        "{%0,%1}, {%2,%3,%4,%5}, {%6,%7}, {%0,%1};"
        : "+r"(c[0]), "+r"(c[1])
        : "r"(a[0]), "r"(a[1]), "r"(a[2]), "r"(a[3]), "r"(b[0]), "r"(b[1]));
}

__device__ __forceinline__ void ldsm4(uint32_t addr, uint32_t* r) {
    asm volatile("ldmatrix.sync.aligned.m8n8.x4.shared.b16 {%0,%1,%2,%3}, [%4];"
                 : "=r"(r[0]), "=r"(r[1]), "=r"(r[2]), "=r"(r[3]) : "r"(addr));
}
__device__ __forceinline__ void ldsm4t(uint32_t addr, uint32_t* r) {
    asm volatile("ldmatrix.sync.aligned.m8n8.x4.trans.shared.b16 {%0,%1,%2,%3}, [%4];"
                 : "=r"(r[0]), "=r"(r[1]), "=r"(r[2]), "=r"(r[3]) : "r"(addr));
}

__device__ __forceinline__ void cp_async16(uint32_t smem_addr, const void* gptr, int src_size) {
    asm volatile("cp.async.cg.shared.global [%0], [%1], 16, %2;"
                 :: "r"(smem_addr), "l"(gptr), "r"(src_size));
}
__device__ __forceinline__ void cp_commit() {
    asm volatile("cp.async.commit_group;" ::: "memory");
}
template <int N>
__device__ __forceinline__ void cp_wait() {
    asm volatile("cp.async.wait_group %0;" :: "n"(N) : "memory");
}

__device__ __forceinline__ float gelu_exact(float v) {
    return 0.5f * v * (1.0f + erff(v * 0.7071067811865476f));
}

// ---------------------------------------------------------------------------
// Prepass: fp32 -> fp16 (RN) streaming convert
// ---------------------------------------------------------------------------
__global__ void cvt_kernel(const float* __restrict__ in, __half* __restrict__ outp, size_t n4) {
    size_t i = (size_t)blockIdx.x * blockDim.x + threadIdx.x;
    size_t stride = (size_t)gridDim.x * blockDim.x;
    for (; i < n4; i += stride) {
        float4 v = ((const float4*)in)[i];
        ((__half2*)outp)[2 * i]     = __floats2half2_rn(v.x, v.y);
        ((__half2*)outp)[2 * i + 1] = __floats2half2_rn(v.z, v.w);
    }
}

// ---------------------------------------------------------------------------
// fp16 grouped GEMM + GELU.  CTA tile 128(m) x 128(n), BK=64, 4-stage cp.async.
// 256 threads = 8 warps: warpM = wid>>1 (4, 32 rows), warpN = wid&1 (2, 64 cols).
// ACC16: accumulate 2 MMAs (K=32) in fp16, spill into persistent fp32 acc.
// MODE 0: A = windowed g_xh[B,P,H] (K=4096, out g_h1h fp16)
// MODE 1: A = g_h1h [p][b][k]      (K=2048, out g_h2  fp32)
// ---------------------------------------------------------------------------
#define BM 128
#define BN 128
#define BK 64
#define ASTRH 72              // A row stride (halves): 144B, LDSM conflict-free
#define BSTRH 136             // B row stride (halves): 272B, LDSM conflict-free
#define ASZB (BM * ASTRH * 2)          // 18432 B
#define BSZB (BK * BSTRH * 2)          // 17408 B
#define STGB (ASZB + BSZB)             // 35840 B / stage
#define NSTG 4
#define SMEM_BYTES (NSTG * STGB)       // 143360

template <int MODE, bool ACC16>
__global__ void __launch_bounds__(256, 1)
gemm_f16_kernel(const __half* __restrict__ A, const __half* __restrict__ W,
                const float* __restrict__ bias, void* __restrict__ Cout,
                int K, int N) {
    extern __shared__ __half smem[];
    const uint32_t smem_u = (uint32_t)__cvta_generic_to_shared(smem);

    const int p    = blockIdx.z;
    const int bm   = blockIdx.y;
    const int bn   = blockIdx.x;
    const int tid  = threadIdx.x;
    const int wid  = tid >> 5;
    const int lane = tid & 31;
    const int warpM = wid >> 1;    // 0..3  (32 rows)
    const int warpN = wid & 1;     // 0..1  (64 cols)
    const int g  = lane >> 2;      // 0..7
    const int cc = lane & 3;       // 0..3

    // ldmatrix lane address components
    const int l7 = lane & 7;
    const int lb = (lane >> 3) & 1;
    const int lk = lane >> 4;
    const uint32_t aoff = ((warpM * 32 + lb * 8 + l7) * ASTRH + lk * 8) * 2;
    const uint32_t boff = ASZB + ((lb * 8 + l7) * BSTRH + warpN * 64 + lk * 8) * 2;

    float acc[2][8][4];
#pragma unroll
    for (int mf = 0; mf < 2; mf++)
#pragma unroll
        for (int nf = 0; nf < 8; nf++)
#pragma unroll
            for (int i = 0; i < 4; i++) acc[mf][nf][i] = 0.f;

    uint32_t acc16[2][8][2];
    if (ACC16) {
#pragma unroll
        for (int mf = 0; mf < 2; mf++)
#pragma unroll
            for (int nf = 0; nf < 8; nf++) { acc16[mf][nf][0] = 0u; acc16[mf][nf][1] = 0u; }
    }

    const __half* Wp = W + (size_t)p * K * N + (size_t)bn * BN;

    auto load_tiles = [&](int kt, int buf) {
        uint32_t sbase = smem_u + buf * STGB;
        // A: 128 rows x 64 halves = 1024 x 16B chunks -> 4 per thread
#pragma unroll
        for (int i = 0; i < 4; i++) {
            int c  = tid + i * 256;
            int m  = c >> 3;
            int kl = (c & 7) * 8;
            int kg = kt * BK + kl;
            const __half* ga;
            int sz = 16;
            if (MODE == 0) {
                int half_ = (kg >= H_) ? 1 : 0;
                int pp    = p + half_;
                int kk    = kg - half_ * H_;
                if (pp >= P_) { pp = P_ - 1; sz = 0; }   // right-edge zero pad
                ga = A + ((size_t)(bm * BM + m) * P_ + pp) * H_ + kk;
            } else {
                ga = A + ((size_t)p * B_ + bm * BM + m) * (size_t)K + kg;
            }
            cp_async16(sbase + (m * ASTRH + kl) * 2, ga, sz);
        }
        // B: 64 rows x 128 halves = 1024 x 16B chunks -> 4 per thread
#pragma unroll
        for (int i = 0; i < 4; i++) {
            int c  = tid + i * 256;
            int kb = c >> 4;              // 0..63
            int nb = (c & 15) * 8;        // 0..120
            const __half* gb = Wp + (size_t)(kt * BK + kb) * N + nb;
            cp_async16(sbase + ASZB + (kb * BSTRH + nb) * 2, gb, 16);
        }
    };

    const int NKT = K / BK;
    load_tiles(0, 0); cp_commit();
    load_tiles(1, 1); cp_commit();
    load_tiles(2, 2); cp_commit();

    uint32_t a[2][2][4], b[2][4][4];

    for (int kt = 0; kt < NKT; ++kt) {
        cp_wait<2>();
        __syncthreads();
        if (kt + 3 < NKT) load_tiles(kt + 3, (kt + 3) & 3);
        cp_commit();                  // possibly-empty group keeps invariant

        const uint32_t sbase = smem_u + (kt & 3) * STGB;
        const uint32_t aB = sbase + aoff;
        const uint32_t bB = sbase + boff;

        // prefetch ks=0 fragments
#pragma unroll
        for (int f = 0; f < 2; f++) ldsm4(aB + f * (16 * ASTRH * 2), a[0][f]);
#pragma unroll
        for (int nf = 0; nf < 4; nf++) ldsm4t(bB + nf * 32, b[0][nf]);

#pragma unroll
        for (int ks = 0; ks < 4; ks++) {
            const int cb = ks & 1;
            if (ks < 3) {
                const int nb2 = cb ^ 1;
                const uint32_t akk = aB + (ks + 1) * 32;
                const uint32_t bkk = bB + (ks + 1) * (16 * BSTRH * 2);
#pragma unroll
                for (int f = 0; f < 2; f++) ldsm4(akk + f * (16 * ASTRH * 2), a[nb2][f]);
#pragma unroll
                for (int nf = 0; nf < 4; nf++) ldsm4t(bkk + nf * 32, b[nb2][nf]);
            }
            if (ACC16) {
#pragma unroll
                for (int mf = 0; mf < 2; mf++)
#pragma unroll
                    for (int nf = 0; nf < 4; nf++) {
                        mma_f16_f16(acc16[mf][2 * nf],     a[cb][mf], &b[cb][nf][0]);
                        mma_f16_f16(acc16[mf][2 * nf + 1], a[cb][mf], &b[cb][nf][2]);
                    }
                if (ks & 1) {
                    // spill f16 partials (K=32 chunk) into fp32 accumulators
#pragma unroll
                    for (int mf = 0; mf < 2; mf++)
#pragma unroll
                        for (int t = 0; t < 8; t++) {
                            float2 f0 = __half22float2(*(__half2*)&acc16[mf][t][0]);
                            float2 f1 = __half22float2(*(__half2*)&acc16[mf][t][1]);
                            acc[mf][t][0] += f0.x; acc[mf][t][1] += f0.y;
                            acc[mf][t][2] += f1.x; acc[mf][t][3] += f1.y;
                            acc16[mf][t][0] = 0u; acc16[mf][t][1] = 0u;
                        }
                }
            } else {
#pragma unroll
                for (int mf = 0; mf < 2; mf++)
#pragma unroll
                    for (int nf = 0; nf < 4; nf++) {
                        mma_f16_f32(acc[mf][2 * nf],     a[cb][mf], &b[cb][nf][0]);
                        mma_f16_f32(acc[mf][2 * nf + 1], a[cb][mf], &b[cb][nf][2]);
                    }
            }
        }
    }

    // Epilogue: bias + exact GELU.  MODE0 -> fp16 h1, MODE1 -> fp32 h2.
    const float* brow = bias + (size_t)p * N;
#pragma unroll
    for (int mf = 0; mf < 2; mf++) {
        int row0 = bm * BM + warpM * 32 + mf * 16 + g;
        size_t base0 = ((size_t)p * B_ + row0) * (size_t)N;
        size_t base8 = base0 + (size_t)8 * N;
#pragma unroll
        for (int nf = 0; nf < 8; nf++) {
            int n = bn * BN + warpN * 64 + nf * 8 + cc * 2;
            float bv0 = __ldg(brow + n);
            float bv1 = __ldg(brow + n + 1);
            float v0 = gelu_exact(acc[mf][nf][0] + bv0);
            float v1 = gelu_exact(acc[mf][nf][1] + bv1);
            float v2 = gelu_exact(acc[mf][nf][2] + bv0);
            float v3 = gelu_exact(acc[mf][nf][3] + bv1);
            if (MODE == 0) {
                __half* C = (__half*)Cout;
                *(__half2*)(C + base0 + n) = __floats2half2_rn(v0, v1);
                *(__half2*)(C + base8 + n) = __floats2half2_rn(v2, v3);
            } else {
                float* C = (float*)Cout;
                *(float2*)(C + base0 + n) = make_float2(v0, v1);
                *(float2*)(C + base8 + n) = make_float2(v2, v3);
            }
        }
    }
}

// ---------------------------------------------------------------------------
// Layer 3: out[b, p*4+o] = relu(sum_k h2[p][b][k] * W3[p][k][o] + b3[p][o])
// ---------------------------------------------------------------------------
__global__ void l3_kernel(const float* __restrict__ h2, const float* __restrict__ W3,
                          const float* __restrict__ b3, float* __restrict__ out) {
    int p = blockIdx.x, b = blockIdx.y;
    int tid = threadIdx.x;
    const float* hrow = h2 + ((size_t)p * B_ + b) * N2_;
    const float* w    = W3 + (size_t)p * N2_ * OUTP;

    float a0 = 0.f, a1 = 0.f, a2 = 0.f, a3 = 0.f;
    for (int k = tid; k < N2_; k += 128) {
        float hv = hrow[k];
        const float* wr = w + k * OUTP;
        a0 += hv * wr[0]; a1 += hv * wr[1]; a2 += hv * wr[2]; a3 += hv * wr[3];
    }
#pragma unroll
    for (int off = 16; off; off >>= 1) {
        a0 += __shfl_down_sync(0xffffffffu, a0, off);
        a1 += __shfl_down_sync(0xffffffffu, a1, off);
        a2 += __shfl_down_sync(0xffffffffu, a2, off);
        a3 += __shfl_down_sync(0xffffffffu, a3, off);
    }
    __shared__ float sred[4][4];
    int warp = tid >> 5, lane = tid & 31;
    if (lane == 0) {
        sred[warp][0] = a0; sred[warp][1] = a1; sred[warp][2] = a2; sred[warp][3] = a3;
    }
    __syncthreads();
    if (tid < 4) {
        float s = sred[0][tid] + sred[1][tid] + sred[2][tid] + sred[3][tid]
                + b3[p * OUTP + tid];
        out[(size_t)b * (P_ * OUTP) + p * OUTP + tid] = fmaxf(s, 0.f);
    }
}

// ---------------------------------------------------------------------------
extern "C" void kernel_launch(void* const* d_in, const int* in_sizes, int n_in,
                              void* d_out, int out_size) {
    const float* x  = (const float*)d_in[0];
    const float* W1 = (const float*)d_in[1];
    const float* b1 = (const float*)d_in[2];
    const float* W2 = (const float*)d_in[3];
    const float* b2 = (const float*)d_in[4];
    const float* W3 = (const float*)d_in[5];
    const float* b3 = (const float*)d_in[6];
    float* out = (float*)d_out;

    __half *xh, *w1h, *w2h, *h1h;
    float *h2;
    cudaGetSymbolAddress((void**)&xh,  g_xh);
    cudaGetSymbolAddress((void**)&w1h, g_w1h);
    cudaGetSymbolAddress((void**)&w2h, g_w2h);
    cudaGetSymbolAddress((void**)&h1h, g_h1h);
    cudaGetSymbolAddress((void**)&h2,  g_h2);

    cudaFuncSetAttribute((const void*)gemm_f16_kernel<0, true>,
                         cudaFuncAttributeMaxDynamicSharedMemorySize, SMEM_BYTES);
    cudaFuncSetAttribute((const void*)gemm_f16_kernel<1, false>,
                         cudaFuncAttributeMaxDynamicSharedMemorySize, SMEM_BYTES);

    // Prepass: fp32 -> fp16 converts (x, W1, W2)
    cvt_kernel<<<2048, 256>>>(x,  xh,  (size_t)B_ * P_ * H_ / 4);
    cvt_kernel<<<8192, 256>>>(W1, w1h, (size_t)P_ * K1_ * N1_ / 4);
    cvt_kernel<<<4096, 256>>>(W2, w2h, (size_t)P_ * K2_ * N2_ / 4);

    // Layer 1: [1024, 4096] @ [4096, 2048] per p, GELU -> fp16 h1 (f16-acc experiment)
    gemm_f16_kernel<0, true><<<dim3(N1_ / BN, B_ / BM, P_), 256, SMEM_BYTES>>>(
        xh, w1h, b1, h1h, K1_, N1_);
    // Layer 2: [1024, 2048] @ [2048, 1024] per p, GELU -> fp32 h2 (f32-acc)
    gemm_f16_kernel<1, false><<<dim3(N2_ / BN, B_ / BM, P_), 256, SMEM_BYTES>>>(
        h1h, w2h, b2, h2, K2_, N2_);
    // Layer 3: tiny N=4 + ReLU
    l3_kernel<<<dim3(P_, B_), 128>>>(h2, W3, b3, out);
}

// round 8
// speedup vs baseline: 1.4038x; 1.4038x over previous
#include <cuda_runtime.h>
#include <cuda_fp16.h>
#include <cstdint>

// Problem constants
#define B_   1024
#define P_   24
#define H_   2048
#define K1_  4096   // H*R
#define N1_  2048   // H
#define K2_  2048
#define N2_  1024   // H/2
#define OUTP 4

// Scratch (allocation-free rule: __device__ globals)
__device__ __half g_xh [(size_t)B_ * P_ * H_];    // x   -> fp16
__device__ __half g_w1h[(size_t)P_ * K1_ * N1_];  // W1  -> fp16
__device__ __half g_w2h[(size_t)P_ * K2_ * N2_];  // W2  -> fp16
__device__ __half g_h1h[(size_t)P_ * B_ * N1_];   // layer1 out fp16
__device__ float  g_h2 [(size_t)P_ * B_ * N2_];   // layer2 out fp32

// ---------------------------------------------------------------------------
// helpers
// ---------------------------------------------------------------------------
__device__ __forceinline__ void mma_f16_f32(float* c, const uint32_t* a, const uint32_t* b) {
    asm volatile(
        "mma.sync.aligned.m16n8k16.row.col.f32.f16.f16.f32 "
        "{%0,%1,%2,%3}, {%4,%5,%6,%7}, {%8,%9}, {%0,%1,%2,%3};"
        : "+f"(c[0]), "+f"(c[1]), "+f"(c[2]), "+f"(c[3])
        : "r"(a[0]), "r"(a[1]), "r"(a[2]), "r"(a[3]), "r"(b[0]), "r"(b[1]));
}

__device__ __forceinline__ void ldsm4(uint32_t addr, uint32_t* r) {
    asm volatile("ldmatrix.sync.aligned.m8n8.x4.shared.b16 {%0,%1,%2,%3}, [%4];"
                 : "=r"(r[0]), "=r"(r[1]), "=r"(r[2]), "=r"(r[3]) : "r"(addr));
}
__device__ __forceinline__ void ldsm4t(uint32_t addr, uint32_t* r) {
    asm volatile("ldmatrix.sync.aligned.m8n8.x4.trans.shared.b16 {%0,%1,%2,%3}, [%4];"
                 : "=r"(r[0]), "=r"(r[1]), "=r"(r[2]), "=r"(r[3]) : "r"(addr));
}

__device__ __forceinline__ void cp_async16(uint32_t smem_addr, const void* gptr, int src_size) {
    asm volatile("cp.async.cg.shared.global [%0], [%1], 16, %2;"
                 :: "r"(smem_addr), "l"(gptr), "r"(src_size));
}
__device__ __forceinline__ void cp_commit() {
    asm volatile("cp.async.commit_group;" ::: "memory");
}
template <int N>
__device__ __forceinline__ void cp_wait() {
    asm volatile("cp.async.wait_group %0;" :: "n"(N) : "memory");
}

__device__ __forceinline__ float gelu_exact(float v) {
    return 0.5f * v * (1.0f + erff(v * 0.7071067811865476f));
}

// ---------------------------------------------------------------------------
// Prepass: fp32 -> fp16 (RN) streaming convert
// ---------------------------------------------------------------------------
__global__ void cvt_kernel(const float* __restrict__ in, __half* __restrict__ outp, size_t n4) {
    size_t i = (size_t)blockIdx.x * blockDim.x + threadIdx.x;
    size_t stride = (size_t)gridDim.x * blockDim.x;
    for (; i < n4; i += stride) {
        float4 v = ((const float4*)in)[i];
        ((__half2*)outp)[2 * i]     = __floats2half2_rn(v.x, v.y);
        ((__half2*)outp)[2 * i + 1] = __floats2half2_rn(v.z, v.w);
    }
}

// ---------------------------------------------------------------------------
// fp16 grouped GEMM + GELU.  CTA tile 128(m) x 128(n), BK=64, 3-stage cp.async.
// 256 threads = 8 warps: warpM = wid>>1 (4, 32 rows), warpN = wid&1 (2, 64 cols).
// TWO CTAs per SM (105 KB smem, <=128 regs) -> independent barrier domains
// overlap each other's pipeline bubbles.
// MODE 0: A = windowed g_xh[B,P,H] (K=4096, out g_h1h fp16)
// MODE 1: A = g_h1h [p][b][k]      (K=2048, out g_h2  fp32)
// ---------------------------------------------------------------------------
#define BM 128
#define BN 128
#define BK 64
#define ASTRH 72              // A row stride (halves): 144B, LDSM conflict-free
#define BSTRH 136             // B row stride (halves): 272B, LDSM conflict-free
#define ASZB (BM * ASTRH * 2)          // 18432 B
#define BSZB (BK * BSTRH * 2)          // 17408 B
#define STGB (ASZB + BSZB)             // 35840 B / stage
#define NSTG 3
#define SMEM_BYTES (NSTG * STGB)       // 107520

template <int MODE>
__global__ void __launch_bounds__(256, 2)
gemm_f16_kernel(const __half* __restrict__ A, const __half* __restrict__ W,
                const float* __restrict__ bias, void* __restrict__ Cout,
                int K, int N) {
    extern __shared__ __half smem[];
    const uint32_t smem_u = (uint32_t)__cvta_generic_to_shared(smem);

    const int p    = blockIdx.z;
    const int bm   = blockIdx.y;
    const int bn   = blockIdx.x;
    const int tid  = threadIdx.x;
    const int wid  = tid >> 5;
    const int lane = tid & 31;
    const int warpM = wid >> 1;    // 0..3  (32 rows)
    const int warpN = wid & 1;     // 0..1  (64 cols)
    const int g  = lane >> 2;      // 0..7
    const int cc = lane & 3;       // 0..3

    // ldmatrix lane address components
    const int l7 = lane & 7;
    const int lb = (lane >> 3) & 1;
    const int lk = lane >> 4;
    const uint32_t aoff = ((warpM * 32 + lb * 8 + l7) * ASTRH + lk * 8) * 2;
    const uint32_t boff = ASZB + ((lb * 8 + l7) * BSTRH + warpN * 64 + lk * 8) * 2;

    float acc[2][8][4];
#pragma unroll
    for (int mf = 0; mf < 2; mf++)
#pragma unroll
        for (int nf = 0; nf < 8; nf++)
#pragma unroll
            for (int i = 0; i < 4; i++) acc[mf][nf][i] = 0.f;

    const __half* Wp = W + (size_t)p * K * N + (size_t)bn * BN;

    auto load_tiles = [&](int kt, int buf) {
        uint32_t sbase = smem_u + buf * STGB;
        // A: 128 rows x 64 halves = 1024 x 16B chunks -> 4 per thread
#pragma unroll
        for (int i = 0; i < 4; i++) {
            int c  = tid + i * 256;
            int m  = c >> 3;
            int kl = (c & 7) * 8;
            int kg = kt * BK + kl;
            const __half* ga;
            int sz = 16;
            if (MODE == 0) {
                int half_ = (kg >= H_) ? 1 : 0;
                int pp    = p + half_;
                int kk    = kg - half_ * H_;
                if (pp >= P_) { pp = P_ - 1; sz = 0; }   // right-edge zero pad
                ga = A + ((size_t)(bm * BM + m) * P_ + pp) * H_ + kk;
            } else {
                ga = A + ((size_t)p * B_ + bm * BM + m) * (size_t)K + kg;
            }
            cp_async16(sbase + (m * ASTRH + kl) * 2, ga, sz);
        }
        // B: 64 rows x 128 halves = 1024 x 16B chunks -> 4 per thread
#pragma unroll
        for (int i = 0; i < 4; i++) {
            int c  = tid + i * 256;
            int kb = c >> 4;              // 0..63
            int nb = (c & 15) * 8;        // 0..120
            const __half* gb = Wp + (size_t)(kt * BK + kb) * N + nb;
            cp_async16(sbase + ASZB + (kb * BSTRH + nb) * 2, gb, 16);
        }
    };

    const int NKT = K / BK;
    load_tiles(0, 0); cp_commit();
    load_tiles(1, 1); cp_commit();

    for (int kt = 0; kt < NKT; ++kt) {
        cp_wait<1>();
        __syncthreads();
        if (kt + 2 < NKT) load_tiles(kt + 2, (kt + 2) % NSTG);
        cp_commit();                  // possibly-empty group keeps invariant

        const uint32_t sbase = smem_u + (kt % NSTG) * STGB;
        const uint32_t aB = sbase + aoff;
        const uint32_t bB = sbase + boff;

#pragma unroll
        for (int ks = 0; ks < 4; ks++) {
            uint32_t a[2][4], b[4][4];
            const uint32_t akk = aB + ks * 32;                   // +16 halves along k
            const uint32_t bkk = bB + ks * (16 * BSTRH * 2);
            ldsm4(akk,                  a[0]);
            ldsm4(akk + 16 * ASTRH * 2, a[1]);
#pragma unroll
            for (int nf = 0; nf < 4; nf++) ldsm4t(bkk + nf * 32, b[nf]);
#pragma unroll
            for (int mf = 0; mf < 2; mf++)
#pragma unroll
                for (int nf = 0; nf < 4; nf++) {
                    mma_f16_f32(acc[mf][2 * nf],     a[mf], &b[nf][0]);
                    mma_f16_f32(acc[mf][2 * nf + 1], a[mf], &b[nf][2]);
                }
        }
    }

    // Epilogue: bias + exact GELU.  MODE0 -> fp16 h1, MODE1 -> fp32 h2.
    const float* brow = bias + (size_t)p * N;
#pragma unroll
    for (int mf = 0; mf < 2; mf++) {
        int row0 = bm * BM + warpM * 32 + mf * 16 + g;
        size_t base0 = ((size_t)p * B_ + row0) * (size_t)N;
        size_t base8 = base0 + (size_t)8 * N;
#pragma unroll
        for (int nf = 0; nf < 8; nf++) {
            int n = bn * BN + warpN * 64 + nf * 8 + cc * 2;
            float bv0 = __ldg(brow + n);
            float bv1 = __ldg(brow + n + 1);
            float v0 = gelu_exact(acc[mf][nf][0] + bv0);
            float v1 = gelu_exact(acc[mf][nf][1] + bv1);
            float v2 = gelu_exact(acc[mf][nf][2] + bv0);
            float v3 = gelu_exact(acc[mf][nf][3] + bv1);
            if (MODE == 0) {
                __half* C = (__half*)Cout;
                *(__half2*)(C + base0 + n) = __floats2half2_rn(v0, v1);
                *(__half2*)(C + base8 + n) = __floats2half2_rn(v2, v3);
            } else {
                float* C = (float*)Cout;
                *(float2*)(C + base0 + n) = make_float2(v0, v1);
                *(float2*)(C + base8 + n) = make_float2(v2, v3);
            }
        }
    }
}

// ---------------------------------------------------------------------------
// Layer 3: out[b, p*4+o] = relu(sum_k h2[p][b][k] * W3[p][k][o] + b3[p][o])
// ---------------------------------------------------------------------------
__global__ void l3_kernel(const float* __restrict__ h2, const float* __restrict__ W3,
                          const float* __restrict__ b3, float* __restrict__ out) {
    int p = blockIdx.x, b = blockIdx.y;
    int tid = threadIdx.x;
    const float* hrow = h2 + ((size_t)p * B_ + b) * N2_;
    const float* w    = W3 + (size_t)p * N2_ * OUTP;

    float a0 = 0.f, a1 = 0.f, a2 = 0.f, a3 = 0.f;
    for (int k = tid; k < N2_; k += 128) {
        float hv = hrow[k];
        const float* wr = w + k * OUTP;
        a0 += hv * wr[0]; a1 += hv * wr[1]; a2 += hv * wr[2]; a3 += hv * wr[3];
    }
#pragma unroll
    for (int off = 16; off; off >>= 1) {
        a0 += __shfl_down_sync(0xffffffffu, a0, off);
        a1 += __shfl_down_sync(0xffffffffu, a1, off);
        a2 += __shfl_down_sync(0xffffffffu, a2, off);
        a3 += __shfl_down_sync(0xffffffffu, a3, off);
    }
    __shared__ float sred[4][4];
    int warp = tid >> 5, lane = tid & 31;
    if (lane == 0) {
        sred[warp][0] = a0; sred[warp][1] = a1; sred[warp][2] = a2; sred[warp][3] = a3;
    }
    __syncthreads();
    if (tid < 4) {
        float s = sred[0][tid] + sred[1][tid] + sred[2][tid] + sred[3][tid]
                + b3[p * OUTP + tid];
        out[(size_t)b * (P_ * OUTP) + p * OUTP + tid] = fmaxf(s, 0.f);
    }
}

// ---------------------------------------------------------------------------
extern "C" void kernel_launch(void* const* d_in, const int* in_sizes, int n_in,
                              void* d_out, int out_size) {
    const float* x  = (const float*)d_in[0];
    const float* W1 = (const float*)d_in[1];
    const float* b1 = (const float*)d_in[2];
    const float* W2 = (const float*)d_in[3];
    const float* b2 = (const float*)d_in[4];
    const float* W3 = (const float*)d_in[5];
    const float* b3 = (const float*)d_in[6];
    float* out = (float*)d_out;

    __half *xh, *w1h, *w2h, *h1h;
    float *h2;
    cudaGetSymbolAddress((void**)&xh,  g_xh);
    cudaGetSymbolAddress((void**)&w1h, g_w1h);
    cudaGetSymbolAddress((void**)&w2h, g_w2h);
    cudaGetSymbolAddress((void**)&h1h, g_h1h);
    cudaGetSymbolAddress((void**)&h2,  g_h2);

    cudaFuncSetAttribute((const void*)gemm_f16_kernel<0>,
                         cudaFuncAttributeMaxDynamicSharedMemorySize, SMEM_BYTES);
    cudaFuncSetAttribute((const void*)gemm_f16_kernel<1>,
                         cudaFuncAttributeMaxDynamicSharedMemorySize, SMEM_BYTES);

    // Prepass: fp32 -> fp16 converts (x, W1, W2)
    cvt_kernel<<<2048, 256>>>(x,  xh,  (size_t)B_ * P_ * H_ / 4);
    cvt_kernel<<<8192, 256>>>(W1, w1h, (size_t)P_ * K1_ * N1_ / 4);
    cvt_kernel<<<4096, 256>>>(W2, w2h, (size_t)P_ * K2_ * N2_ / 4);

    // Layer 1: [1024, 4096] @ [4096, 2048] per p, GELU -> fp16 h1
    gemm_f16_kernel<0><<<dim3(N1_ / BN, B_ / BM, P_), 256, SMEM_BYTES>>>(
        xh, w1h, b1, h1h, K1_, N1_);
    // Layer 2: [1024, 2048] @ [2048, 1024] per p, GELU -> fp32 h2
    gemm_f16_kernel<1><<<dim3(N2_ / BN, B_ / BM, P_), 256, SMEM_BYTES>>>(
        h1h, w2h, b2, h2, K2_, N2_);
    // Layer 3: tiny N=4 + ReLU
    l3_kernel<<<dim3(P_, B_), 128>>>(h2, W3, b3, out);
}